// round 3
// baseline (speedup 1.0000x reference)
#include <cuda_runtime.h>
#include <math.h>

// Problem constants
#define Bc 8
#define Nn 8192
#define Sc 2048
#define Kc 32
#define Dc 64
#define PP (Bc*Sc*Kc)   // 524288 positions per channel

// ---------------- scratch (device globals; no allocations allowed) ----------
__device__ float g_X0[8   * PP];   // rif features        16.8 MB
__device__ float g_Y1[32  * PP];   // fe1 pre-BN          67 MB
__device__ float g_Y2[64  * PP];   // fe2 pre-BN          134 MB
__device__ float g_Y3[128 * PP];   // fl1 pre-BN          268 MB
__device__ float g_Y4[256 * PP];   // fl2 pre-BN          537 MB
__device__ int   g_sidx[Sc];
__device__ int   g_gidx[Sc*Kc];
__device__ double g_sum[4][256];
__device__ double g_sq [4][256];
__device__ float g_scale[4][256];
__device__ float g_shift[4][256];

// ---------------------------------------------------------------------------
// k_prep: sample indices (exact fp32 linspace replication), group indices,
//         sampled / new_LOA outputs, and zeroing of the stats accumulators.
// ---------------------------------------------------------------------------
__global__ void k_prep(const float* __restrict__ contour,
                       const float* __restrict__ loa,
                       float* __restrict__ out)
{
    int tid = blockIdx.x * blockDim.x + threadIdx.x;   // 0..65535
    if (tid < 1024) {                                  // zero stats
        ((double*)g_sum)[tid] = 0.0;
        ((double*)g_sq )[tid] = 0.0;
    }
    int s = tid >> 5;
    int k = tid & 31;
    int i0;
    if (s == Sc - 1) {
        i0 = Nn - 1;
    } else {
        // jnp.linspace: t = fl(s/2047); v = fl(0*(1-t) + 8191*t); trunc to int32
        float t = __fdiv_rn((float)s, 2047.0f);
        float v = __fmul_rn(8191.0f, t);
        i0 = (int)v;   // truncation toward zero (values >= 0)
    }
    int g = (i0 - (Kc/2) + k) & (Nn - 1);
    g_gidx[tid] = g;
    if (k == 0) g_sidx[s] = i0;
    if (k < 3) {
        #pragma unroll
        for (int b = 0; b < Bc; ++b) {
            out[(b*Sc + s)*3 + k]              = contour[((size_t)b*Nn + i0)*3 + k];
            out[Bc*Sc*3 + (b*Sc + s)*3 + k]    = loa    [((size_t)b*Nn + i0)*3 + k];
        }
    }
}

__device__ __forceinline__ float clamp_ac(float x) {
    return fminf(fmaxf(x, -0.9999999f), 0.9999999f);
}

// ---------------------------------------------------------------------------
// k_rif: one warp per (b,s); lane = k. Computes the 8 rotation-invariant
//        features and writes them as [8][P], p = (b*S+s)*K + k.
// ---------------------------------------------------------------------------
__global__ void __launch_bounds__(256) k_rif(const float* __restrict__ contour,
                                             const float* __restrict__ loa)
{
    const unsigned FULL = 0xffffffffu;
    int w    = blockIdx.x * 8 + (threadIdx.x >> 5);
    int lane = threadIdx.x & 31;
    int b = w >> 11;           // S = 2048
    int s = w & (Sc - 1);

    int i0 = g_sidx[s];
    const float* cp = contour + ((size_t)b*Nn + i0)*3;
    float spx = cp[0], spy = cp[1], spz = cp[2];
    const float* ap = loa + ((size_t)b*Nn + i0)*3;
    float ax = ap[0], ay = ap[1], az = ap[2];

    int n = g_gidx[s*Kc + lane];
    const float* pp_ = contour + ((size_t)b*Nn + n)*3;
    float lx = pp_[0] - spx, ly = pp_[1] - spy, lz = pp_[2] - spz;
    const float* lp = loa + ((size_t)b*Nn + n)*3;
    float nlx = lp[0], nly = lp[1], nlz = lp[2];

    // d1, unit
    float sq = lx*lx + ly*ly + lz*lz;
    float d1 = (sq > 0.f) ? sqrtf(sq) : 0.f;
    float inv = (d1 > 0.f) ? (1.f / d1) : 0.f;
    float ux = lx*inv, uy = ly*inv, uz = lz*inv;

    int pl = (lane + 31) & 31;   // k-1 (wrap)
    float plx = __shfl_sync(FULL, lx, pl);
    float ply = __shfl_sync(FULL, ly, pl);
    float plz = __shfl_sync(FULL, lz, pl);
    float pnlx = __shfl_sync(FULL, nlx, pl);
    float pnly = __shfl_sync(FULL, nly, pl);
    float pnlz = __shfl_sync(FULL, nlz, pl);
    float pux = __shfl_sync(FULL, ux, pl);
    float puy = __shfl_sync(FULL, uy, pl);
    float puz = __shfl_sync(FULL, uz, pl);

    float ivx = lx - plx, ivy = ly - ply, ivz = lz - plz;
    float isq = ivx*ivx + ivy*ivy + ivz*ivz;
    float idn = (isq > 0.f) ? sqrtf(isq) : 0.f;
    float ii  = (idn > 0.f) ? (1.f / idn) : 0.f;
    float iux = ivx*ii, iuy = ivy*ii, iuz = ivz*ii;

    float a1 = ux*ax + uy*ay + uz*az;
    float a2 = ux*nlx + uy*nly + uz*nlz;
    float a3 = acosf(clamp_ac(nlx*ax + nly*ay + nlz*az));
    float a4 = iux*nlx + iuy*nly + iuz*nlz;
    float a5 = iux*pnlx + iuy*pnly + iuz*pnlz;
    float a6 = acosf(clamp_ac(nlx*pnlx + nly*pnly + nlz*pnlz));
    float d2 = acosf(clamp_ac(ux*pux + uy*puy + uz*puz));

    size_t p = (size_t)(b*Sc + s)*Kc + lane;
    g_X0[0*(size_t)PP + p] = d1;
    g_X0[1*(size_t)PP + p] = d2;
    g_X0[2*(size_t)PP + p] = a1;
    g_X0[3*(size_t)PP + p] = a2;
    g_X0[4*(size_t)PP + p] = a3;
    g_X0[5*(size_t)PP + p] = a4;
    g_X0[6*(size_t)PP + p] = a5;
    g_X0[7*(size_t)PP + p] = a6;
}

// ---------------------------------------------------------------------------
// Fused conv(1x1) + batch-stat accumulation. Input transform applied on the
// shared-memory load: MODE 0 = raw, MODE 1 = BN+ReLU of previous layer,
// MODE 2 = first 64 ch BN+ReLU(Y2), ch 64..127 gathered from feature_maps.
// Block: TILE_O out-channels x 128 positions; 256 threads (8 warps).
// ---------------------------------------------------------------------------
template<int CIN, int COUT, int TILE_O, int MODE, int LAYER>
__global__ void __launch_bounds__(256) k_conv(const float* __restrict__ W,
                                              const float* __restrict__ bias,
                                              const float* __restrict__ fmaps)
{
    constexpr int OW = TILE_O / 8;
    constexpr int PL = (LAYER > 0) ? (LAYER - 1) : 0;

    const float* Xin;
    float* Yout;
    if      (LAYER == 0) { Xin = g_X0; Yout = g_Y1; }
    else if (LAYER == 1) { Xin = g_Y1; Yout = g_Y2; }
    else if (LAYER == 2) { Xin = g_Y2; Yout = g_Y3; }
    else                 { Xin = g_Y3; Yout = g_Y4; }

    __shared__ float sW[TILE_O * 8];
    __shared__ float sX[8 * 128];
    __shared__ float sSc[CIN];
    __shared__ float sSh[CIN];
    __shared__ int   sN[128];

    int tid = threadIdx.x;
    int o0  = blockIdx.y * TILE_O;
    int p0  = blockIdx.x * 128;
    int bb  = p0 >> 16;                 // 65536 positions per batch

    if (MODE >= 1) {
        if (tid < CIN) { sSc[tid] = g_scale[PL][tid]; sSh[tid] = g_shift[PL][tid]; }
    }
    if (MODE == 2) {
        if (tid < 128) sN[tid] = g_gidx[(p0 & 65535) + tid];
    }
    __syncthreads();

    int tx = tid & 31, ty = tid >> 5;
    float4 acc[OW];
    #pragma unroll
    for (int i = 0; i < OW; ++i) acc[i] = make_float4(0.f, 0.f, 0.f, 0.f);

    #pragma unroll
    for (int cc = 0; cc < CIN/8; ++cc) {
        int c0 = cc * 8;
        for (int idx = tid; idx < TILE_O*8; idx += 256) {
            int o = idx >> 3, c = idx & 7;
            sW[idx] = W[(o0 + o)*CIN + c0 + c];
        }
        #pragma unroll
        for (int j = 0; j < 4; ++j) {
            int idx = tid + j*256;
            int kc = idx >> 7, pp = idx & 127;
            int c = c0 + kc;
            float v;
            if (MODE == 0) {
                v = Xin[(size_t)c*PP + p0 + pp];
            } else if (MODE == 1) {
                float r = Xin[(size_t)c*PP + p0 + pp];
                v = fmaxf(fmaf(r, sSc[c], sSh[c]), 0.f);
            } else {
                if (c < 64) {
                    float r = Xin[(size_t)c*PP + p0 + pp];
                    v = fmaxf(fmaf(r, sSc[c], sSh[c]), 0.f);
                } else {
                    v = fmaps[((size_t)bb*Dc + (c - 64))*Nn + sN[pp]];
                }
            }
            sX[idx] = v;
        }
        __syncthreads();

        #pragma unroll
        for (int kc = 0; kc < 8; ++kc) {
            float4 xv = *(const float4*)&sX[kc*128 + tx*4];
            #pragma unroll
            for (int i = 0; i < OW; ++i) {
                float wv = sW[(ty*OW + i)*8 + kc];
                acc[i].x = fmaf(wv, xv.x, acc[i].x);
                acc[i].y = fmaf(wv, xv.y, acc[i].y);
                acc[i].z = fmaf(wv, xv.z, acc[i].z);
                acc[i].w = fmaf(wv, xv.w, acc[i].w);
            }
        }
        __syncthreads();
    }

    // epilogue: bias, store pre-BN y, accumulate per-channel sum / sumsq
    #pragma unroll
    for (int i = 0; i < OW; ++i) {
        int o = o0 + ty*OW + i;
        float bo = bias[o];
        float4 y = acc[i];
        y.x += bo; y.y += bo; y.z += bo; y.w += bo;
        *(float4*)&Yout[(size_t)o*PP + p0 + tx*4] = y;
        float s1 = y.x + y.y + y.z + y.w;
        float s2 = y.x*y.x + y.y*y.y + y.z*y.z + y.w*y.w;
        #pragma unroll
        for (int off = 16; off; off >>= 1) {
            s1 += __shfl_xor_sync(0xffffffffu, s1, off);
            s2 += __shfl_xor_sync(0xffffffffu, s2, off);
        }
        if (tx == 0) {
            atomicAdd(&g_sum[LAYER][o], (double)s1);
            atomicAdd(&g_sq [LAYER][o], (double)s2);
        }
    }
}

// ---------------------------------------------------------------------------
__global__ void k_finalize(int layer, const float* __restrict__ gamma,
                           const float* __restrict__ beta, int cout)
{
    int c = threadIdx.x;
    if (c < cout) {
        double mean = g_sum[layer][c] / (double)PP;
        double var  = g_sq [layer][c] / (double)PP - mean*mean;
        double invs = rsqrt(var + 1e-5);
        double sc   = (double)gamma[c] * invs;
        g_scale[layer][c] = (float)sc;
        g_shift[layer][c] = (float)((double)beta[c] - mean * sc);
    }
}

// ---------------------------------------------------------------------------
// k_maxout: apply BN+ReLU of layer 3 and reduce max over K=32.
// out[(b*256+o)*S + s], contiguous K run per thread (8x float4).
// ---------------------------------------------------------------------------
__global__ void __launch_bounds__(256) k_maxout(float* __restrict__ out)
{
    int t = blockIdx.x * blockDim.x + threadIdx.x;   // over 8*256*2048
    if (t >= Bc*256*Sc) return;
    int s = t & (Sc - 1);
    int o = (t >> 11) & 255;
    int b = t >> 19;
    const float4* src = (const float4*)&g_Y4[(size_t)o*PP + ((size_t)b*Sc + s)*Kc];
    float sc = g_scale[3][o], sh = g_shift[3][o];
    float m = 0.f;   // relu floor
    #pragma unroll
    for (int j = 0; j < 8; ++j) {
        float4 v = src[j];
        m = fmaxf(m, fmaf(v.x, sc, sh));
        m = fmaxf(m, fmaf(v.y, sc, sh));
        m = fmaxf(m, fmaf(v.z, sc, sh));
        m = fmaxf(m, fmaf(v.w, sc, sh));
    }
    out[2*Bc*Sc*3 + t] = m;
}

// ---------------------------------------------------------------------------
extern "C" void kernel_launch(void* const* d_in, const int* in_sizes, int n_in,
                              void* d_out, int out_size)
{
    const float* contour = (const float*)d_in[0];
    const float* loa     = (const float*)d_in[1];
    const float* fmaps   = (const float*)d_in[2];
    const float* fe_w1   = (const float*)d_in[3];
    const float* fe_b1   = (const float*)d_in[4];
    const float* fe_g1   = (const float*)d_in[5];
    const float* fe_be1  = (const float*)d_in[6];
    const float* fe_w2   = (const float*)d_in[7];
    const float* fe_b2   = (const float*)d_in[8];
    const float* fe_g2   = (const float*)d_in[9];
    const float* fe_be2  = (const float*)d_in[10];
    const float* fl_w1   = (const float*)d_in[11];
    const float* fl_b1   = (const float*)d_in[12];
    const float* fl_g1   = (const float*)d_in[13];
    const float* fl_be1  = (const float*)d_in[14];
    const float* fl_w2   = (const float*)d_in[15];
    const float* fl_b2   = (const float*)d_in[16];
    const float* fl_g2   = (const float*)d_in[17];
    const float* fl_be2  = (const float*)d_in[18];
    float* out = (float*)d_out;

    const int PBLK = PP / 128;   // 4096

    k_prep<<<256, 256>>>(contour, loa, out);
    k_rif<<<Bc*Sc/8, 256>>>(contour, loa);

    k_conv<8,   32,  32, 0, 0><<<dim3(PBLK, 1), 256>>>(fe_w1, fe_b1, nullptr);
    k_finalize<<<1, 256>>>(0, fe_g1, fe_be1, 32);

    k_conv<32,  64,  64, 1, 1><<<dim3(PBLK, 1), 256>>>(fe_w2, fe_b2, nullptr);
    k_finalize<<<1, 256>>>(1, fe_g2, fe_be2, 64);

    k_conv<128, 128, 128, 2, 2><<<dim3(PBLK, 1), 256>>>(fl_w1, fl_b1, fmaps);
    k_finalize<<<1, 256>>>(2, fl_g1, fl_be1, 128);

    k_conv<128, 256, 128, 1, 3><<<dim3(PBLK, 2), 256>>>(fl_w2, fl_b2, nullptr);
    k_finalize<<<1, 256>>>(3, fl_g2, fl_be2, 256);

    k_maxout<<<(Bc*256*Sc + 255)/256, 256>>>(out);
}

// round 5
// speedup vs baseline: 1.7499x; 1.7499x over previous
#include <cuda_runtime.h>
#include <math.h>

// Problem constants
#define Bc 8
#define Nn 8192
#define Sc 2048
#define Kc 32
#define Dc 64
#define PP (Bc*Sc*Kc)   // 524288 positions per channel
#define NG (PP/32)      // 16384 k-groups (one per (b,s))

// ---------------- scratch (device globals; no allocations allowed) ----------
__device__ float g_X0[8   * PP];   // rif features        16.8 MB
__device__ float g_Y1[32  * PP];   // fe1 pre-BN          67 MB
__device__ float g_Y2[64  * PP];   // fe2 pre-BN          134 MB
__device__ float g_Y3[128 * PP];   // fl1 pre-BN          268 MB
__device__ float g_mx[256 * NG];   // fl2 per-group max   16.8 MB
__device__ float g_mn[256 * NG];   // fl2 per-group min   16.8 MB
__device__ int   g_gidx[Sc*Kc];
__device__ double g_sum[4][256];
__device__ double g_sq [4][256];
__device__ float g_scale[4][256];
__device__ float g_shift[4][256];

__device__ __forceinline__ float clamp_ac(float x) {
    return fminf(fmaxf(x, -0.9999999f), 0.9999999f);
}

// ---------------------------------------------------------------------------
// k_rif (fused prep): one warp per (b,s); lane = k. Computes sample index
// inline (exact fp32 linspace replication), the 8 rotation-invariant
// features, sampled/new_LOA outputs, g_gidx, and zeroes the stat buffers.
// ---------------------------------------------------------------------------
__global__ void __launch_bounds__(256) k_rif(const float* __restrict__ contour,
                                             const float* __restrict__ loa,
                                             float* __restrict__ out)
{
    const unsigned FULL = 0xffffffffu;
    int tid  = threadIdx.x;
    if (blockIdx.x == 0) {                       // zero stats (1024 doubles x2)
        #pragma unroll
        for (int j = 0; j < 4; ++j) {
            ((double*)g_sum)[tid + j*256] = 0.0;
            ((double*)g_sq )[tid + j*256] = 0.0;
        }
    }
    int w    = blockIdx.x * 8 + (tid >> 5);
    int lane = tid & 31;
    int b = w >> 11;           // S = 2048
    int s = w & (Sc - 1);

    int i0;
    if (s == Sc - 1) {
        i0 = Nn - 1;
    } else {
        // jnp.linspace: t = fl(s/2047); v = fl(8191*t); trunc to int32
        float t = __fdiv_rn((float)s, 2047.0f);
        float v = __fmul_rn(8191.0f, t);
        i0 = (int)v;
    }
    int n = (i0 - (Kc/2) + lane) & (Nn - 1);
    if (b == 0) g_gidx[s*Kc + lane] = n;

    const float* cp = contour + ((size_t)b*Nn + i0)*3;
    float spx = cp[0], spy = cp[1], spz = cp[2];
    const float* ap = loa + ((size_t)b*Nn + i0)*3;
    float ax = ap[0], ay = ap[1], az = ap[2];

    if (lane < 3) {
        out[(b*Sc + s)*3 + lane]           = cp[lane];
        out[Bc*Sc*3 + (b*Sc + s)*3 + lane] = ap[lane];
    }

    const float* pp_ = contour + ((size_t)b*Nn + n)*3;
    float lx = pp_[0] - spx, ly = pp_[1] - spy, lz = pp_[2] - spz;
    const float* lp = loa + ((size_t)b*Nn + n)*3;
    float nlx = lp[0], nly = lp[1], nlz = lp[2];

    float sq = lx*lx + ly*ly + lz*lz;
    float d1 = (sq > 0.f) ? sqrtf(sq) : 0.f;
    float inv = (d1 > 0.f) ? (1.f / d1) : 0.f;
    float ux = lx*inv, uy = ly*inv, uz = lz*inv;

    int pl = (lane + 31) & 31;   // k-1 (wrap)
    float plx = __shfl_sync(FULL, lx, pl);
    float ply = __shfl_sync(FULL, ly, pl);
    float plz = __shfl_sync(FULL, lz, pl);
    float pnlx = __shfl_sync(FULL, nlx, pl);
    float pnly = __shfl_sync(FULL, nly, pl);
    float pnlz = __shfl_sync(FULL, nlz, pl);
    float pux = __shfl_sync(FULL, ux, pl);
    float puy = __shfl_sync(FULL, uy, pl);
    float puz = __shfl_sync(FULL, uz, pl);

    float ivx = lx - plx, ivy = ly - ply, ivz = lz - plz;
    float isq = ivx*ivx + ivy*ivy + ivz*ivz;
    float idn = (isq > 0.f) ? sqrtf(isq) : 0.f;
    float ii  = (idn > 0.f) ? (1.f / idn) : 0.f;
    float iux = ivx*ii, iuy = ivy*ii, iuz = ivz*ii;

    float a1 = ux*ax + uy*ay + uz*az;
    float a2 = ux*nlx + uy*nly + uz*nlz;
    float a3 = acosf(clamp_ac(nlx*ax + nly*ay + nlz*az));
    float a4 = iux*nlx + iuy*nly + iuz*nlz;
    float a5 = iux*pnlx + iuy*pnly + iuz*pnlz;
    float a6 = acosf(clamp_ac(nlx*pnlx + nly*pnly + nlz*pnlz));
    float d2 = acosf(clamp_ac(ux*pux + uy*puy + uz*puz));

    size_t p = (size_t)(b*Sc + s)*Kc + lane;
    g_X0[0*(size_t)PP + p] = d1;
    g_X0[1*(size_t)PP + p] = d2;
    g_X0[2*(size_t)PP + p] = a1;
    g_X0[3*(size_t)PP + p] = a2;
    g_X0[4*(size_t)PP + p] = a3;
    g_X0[5*(size_t)PP + p] = a4;
    g_X0[6*(size_t)PP + p] = a5;
    g_X0[7*(size_t)PP + p] = a6;
}

// ---------------------------------------------------------------------------
// Fused conv(1x1) + batch-stat accumulation, register-tiled SGEMM.
// Block = TILE_O out-channels x 128 positions, 256 threads (16x16).
// Thread microtile: OW = TILE_O/16 outputs x 8 positions.
// MODE 0 = raw input, MODE 1 = BN+ReLU of previous layer,
// MODE 2 = ch<64 BN+ReLU(Y2), ch 64..127 gathered from feature_maps.
// LAYER 3 epilogue reduces per-k-group max/min instead of storing Y.
// ---------------------------------------------------------------------------
template<int CIN, int COUT, int TILE_O, int MODE, int LAYER>
__global__ void __launch_bounds__(256) k_conv(const float* __restrict__ W,
                                              const float* __restrict__ bias,
                                              const float* __restrict__ fmaps)
{
    constexpr int OW = TILE_O / 16;
    constexpr int PL = (LAYER > 0) ? (LAYER - 1) : 0;

    const float* Xin;
    float* Yout;
    if      (LAYER == 0) { Xin = g_X0; Yout = g_Y1; }
    else if (LAYER == 1) { Xin = g_Y1; Yout = g_Y2; }
    else if (LAYER == 2) { Xin = g_Y2; Yout = g_Y3; }
    else                 { Xin = g_Y3; Yout = nullptr; }

    __shared__ __align__(16) float sW[8][TILE_O];
    __shared__ __align__(16) float sX[8][128];
    __shared__ float sSc[CIN];
    __shared__ float sSh[CIN];
    __shared__ int   sN[128];

    int tid = threadIdx.x;
    int o0  = blockIdx.y * TILE_O;
    int p0  = blockIdx.x * 128;
    int bb  = p0 >> 16;                 // 65536 positions per batch

    if (MODE >= 1) {
        if (tid < CIN) { sSc[tid] = g_scale[PL][tid]; sSh[tid] = g_shift[PL][tid]; }
    }
    if (MODE == 2) {
        if (tid < 128) sN[tid] = g_gidx[(p0 & 65535) + tid];
    }
    __syncthreads();   // sSc/sSh/sN visible to all threads before mainloop reads

    int tx = tid & 15, ty = tid >> 4;
    int kcl = tid >> 5;          // 0..7  (X-fill channel)
    int pp4 = (tid & 31) * 4;    // 0..124 (X-fill position, float4)

    float acc[OW][8];
    #pragma unroll
    for (int i = 0; i < OW; ++i)
        #pragma unroll
        for (int j = 0; j < 8; ++j) acc[i][j] = 0.f;

    #pragma unroll 1
    for (int cc = 0; cc < CIN/8; ++cc) {
        int c0 = cc * 8;
        // weights: sW[c][o]  (transposed for vector loads in compute)
        for (int idx = tid; idx < TILE_O*8; idx += 256) {
            int o = idx & (TILE_O - 1), c = idx / TILE_O;
            sW[c][o] = W[(o0 + o)*CIN + c0 + c];
        }
        // X: one float4 per thread
        {
            int c = c0 + kcl;
            float4 v;
            if (MODE == 0) {
                v = *(const float4*)&Xin[(size_t)c*PP + p0 + pp4];
            } else if (MODE == 1 || (MODE == 2 && c0 + kcl < 64)) {
                float4 r = *(const float4*)&Xin[(size_t)c*PP + p0 + pp4];
                float scv = sSc[c], shv = sSh[c];
                v.x = fmaxf(fmaf(r.x, scv, shv), 0.f);
                v.y = fmaxf(fmaf(r.y, scv, shv), 0.f);
                v.z = fmaxf(fmaf(r.z, scv, shv), 0.f);
                v.w = fmaxf(fmaf(r.w, scv, shv), 0.f);
            } else {
                const float* fp = fmaps + ((size_t)bb*Dc + (c - 64))*Nn;
                v.x = fp[sN[pp4 + 0]];
                v.y = fp[sN[pp4 + 1]];
                v.z = fp[sN[pp4 + 2]];
                v.w = fp[sN[pp4 + 3]];
            }
            *(float4*)&sX[kcl][pp4] = v;
        }
        __syncthreads();

        #pragma unroll
        for (int kc = 0; kc < 8; ++kc) {
            float4 xa = ((const float4*)sX[kc])[tx*2];
            float4 xb = ((const float4*)sX[kc])[tx*2 + 1];
            float xr[8] = {xa.x, xa.y, xa.z, xa.w, xb.x, xb.y, xb.z, xb.w};
            float wr[OW];
            if constexpr (OW == 8) {
                float4 wa = ((const float4*)sW[kc])[ty*2];
                float4 wb = ((const float4*)sW[kc])[ty*2 + 1];
                wr[0]=wa.x; wr[1]=wa.y; wr[2]=wa.z; wr[3]=wa.w;
                wr[4]=wb.x; wr[5]=wb.y; wr[6]=wb.z; wr[7]=wb.w;
            } else if constexpr (OW == 4) {
                float4 wa = ((const float4*)sW[kc])[ty];
                wr[0]=wa.x; wr[1]=wa.y; wr[2]=wa.z; wr[3]=wa.w;
            } else {
                #pragma unroll
                for (int i = 0; i < OW; ++i) wr[i] = sW[kc][ty*OW + i];
            }
            #pragma unroll
            for (int i = 0; i < OW; ++i)
                #pragma unroll
                for (int j = 0; j < 8; ++j)
                    acc[i][j] = fmaf(wr[i], xr[j], acc[i][j]);
        }
        __syncthreads();
    }

    // epilogue: bias; store Y (layers 0-2) or k-group max/min (layer 3);
    // accumulate per-channel sum / sumsq.
    #pragma unroll
    for (int i = 0; i < OW; ++i) {
        int o = o0 + ty*OW + i;
        float bo = bias[o];
        float y[8];
        #pragma unroll
        for (int j = 0; j < 8; ++j) y[j] = acc[i][j] + bo;

        if (LAYER < 3) {
            *(float4*)&Yout[(size_t)o*PP + p0 + tx*8]     = make_float4(y[0], y[1], y[2], y[3]);
            *(float4*)&Yout[(size_t)o*PP + p0 + tx*8 + 4] = make_float4(y[4], y[5], y[6], y[7]);
        } else {
            float mx = y[0], mn = y[0];
            #pragma unroll
            for (int j = 1; j < 8; ++j) { mx = fmaxf(mx, y[j]); mn = fminf(mn, y[j]); }
            // combine 4 tx-lanes covering one 32-position k-group
            #pragma unroll
            for (int off = 1; off <= 2; off <<= 1) {
                mx = fmaxf(mx, __shfl_xor_sync(0xffffffffu, mx, off));
                mn = fminf(mn, __shfl_xor_sync(0xffffffffu, mn, off));
            }
            if ((tx & 3) == 0) {
                int grp = (p0 >> 5) + (tx >> 2);
                g_mx[(size_t)o*NG + grp] = mx;
                g_mn[(size_t)o*NG + grp] = mn;
            }
        }

        float s1 = 0.f, s2 = 0.f;
        #pragma unroll
        for (int j = 0; j < 8; ++j) { s1 += y[j]; s2 += y[j]*y[j]; }
        #pragma unroll
        for (int off = 1; off <= 8; off <<= 1) {
            s1 += __shfl_xor_sync(0xffffffffu, s1, off);
            s2 += __shfl_xor_sync(0xffffffffu, s2, off);
        }
        if (tx == 0) {
            atomicAdd(&g_sum[LAYER][o], (double)s1);
            atomicAdd(&g_sq [LAYER][o], (double)s2);
        }
    }
}

// ---------------------------------------------------------------------------
__global__ void k_finalize(int layer, const float* __restrict__ gamma,
                           const float* __restrict__ beta, int cout)
{
    int c = threadIdx.x;
    if (c < cout) {
        double mean = g_sum[layer][c] / (double)PP;
        double var  = g_sq [layer][c] / (double)PP - mean*mean;
        double invs = rsqrt(var + 1e-5);
        double sc   = (double)gamma[c] * invs;
        g_scale[layer][c] = (float)sc;
        g_shift[layer][c] = (float)((double)beta[c] - mean * sc);
    }
}

// ---------------------------------------------------------------------------
// k_out: out[(b*256+o)*S + s] = relu(sc>0 ? sc*mx+sh : sc*mn+sh)
// ---------------------------------------------------------------------------
__global__ void __launch_bounds__(256) k_out(float* __restrict__ out)
{
    int t = blockIdx.x * blockDim.x + threadIdx.x;   // over 8*256*2048
    if (t >= Bc*256*Sc) return;
    int s = t & (Sc - 1);
    int o = (t >> 11) & 255;
    int b = t >> 19;
    float sc = g_scale[3][o], sh = g_shift[3][o];
    int grp = b*Sc + s;
    float v = (sc > 0.f) ? g_mx[(size_t)o*NG + grp] : g_mn[(size_t)o*NG + grp];
    out[2*Bc*Sc*3 + t] = fmaxf(fmaf(v, sc, sh), 0.f);
}

// ---------------------------------------------------------------------------
extern "C" void kernel_launch(void* const* d_in, const int* in_sizes, int n_in,
                              void* d_out, int out_size)
{
    const float* contour = (const float*)d_in[0];
    const float* loa     = (const float*)d_in[1];
    const float* fmaps   = (const float*)d_in[2];
    const float* fe_w1   = (const float*)d_in[3];
    const float* fe_b1   = (const float*)d_in[4];
    const float* fe_g1   = (const float*)d_in[5];
    const float* fe_be1  = (const float*)d_in[6];
    const float* fe_w2   = (const float*)d_in[7];
    const float* fe_b2   = (const float*)d_in[8];
    const float* fe_g2   = (const float*)d_in[9];
    const float* fe_be2  = (const float*)d_in[10];
    const float* fl_w1   = (const float*)d_in[11];
    const float* fl_b1   = (const float*)d_in[12];
    const float* fl_g1   = (const float*)d_in[13];
    const float* fl_be1  = (const float*)d_in[14];
    const float* fl_w2   = (const float*)d_in[15];
    const float* fl_b2   = (const float*)d_in[16];
    const float* fl_g2   = (const float*)d_in[17];
    const float* fl_be2  = (const float*)d_in[18];
    float* out = (float*)d_out;

    const int PBLK = PP / 128;   // 4096

    k_rif<<<Bc*Sc/8, 256>>>(contour, loa, out);                       // launch 0

    k_conv<8,   32,  32, 0, 0><<<dim3(PBLK, 1), 256>>>(fe_w1, fe_b1, nullptr);  // 1
    k_finalize<<<1, 256>>>(0, fe_g1, fe_be1, 32);                               // 2

    k_conv<32,  64,  64, 1, 1><<<dim3(PBLK, 1), 256>>>(fe_w2, fe_b2, nullptr);  // 3
    k_finalize<<<1, 256>>>(1, fe_g2, fe_be2, 64);                               // 4

    k_conv<128, 128, 128, 2, 2><<<dim3(PBLK, 1), 256>>>(fl_w1, fl_b1, fmaps);   // 5 (ncu)
    k_finalize<<<1, 256>>>(2, fl_g1, fl_be1, 128);                              // 6

    k_conv<128, 256, 128, 1, 3><<<dim3(PBLK, 2), 256>>>(fl_w2, fl_b2, nullptr); // 7
    k_finalize<<<1, 256>>>(3, fl_g2, fl_be2, 256);                              // 8

    k_out<<<(Bc*256*Sc + 255)/256, 256>>>(out);                                 // 9
}

// round 6
// speedup vs baseline: 1.7518x; 1.0011x over previous
#include <cuda_runtime.h>
#include <math.h>

// Problem constants
#define Bc 8
#define Nn 8192
#define Sc 2048
#define Kc 32
#define Dc 64
#define PP (Bc*Sc*Kc)   // 524288 positions per channel
#define NG (PP/32)      // 16384 k-groups (one per (b,s))

// ---------------- scratch (device globals; no allocations allowed) ----------
__device__ float g_X0[8   * PP];   // rif features        16.8 MB
__device__ float g_Y1[32  * PP];   // fe1 pre-BN          67 MB
__device__ float g_Y2[64  * PP];   // fe2 pre-BN          134 MB
__device__ float g_Y3[128 * PP];   // fl1 pre-BN          268 MB
__device__ float g_mx[256 * NG];   // fl2 per-group max   16.8 MB
__device__ float g_mn[256 * NG];   // fl2 per-group min   16.8 MB
__device__ int   g_gidx[Sc*Kc];
__device__ double g_sum[4][256];
__device__ double g_sq [4][256];
__device__ float g_scale[4][256];
__device__ float g_shift[4][256];

__device__ __forceinline__ float clamp_ac(float x) {
    return fminf(fmaxf(x, -0.9999999f), 0.9999999f);
}

// ---------------------------------------------------------------------------
// k_rif (fused prep): one warp per (b,s); lane = k. Computes sample index
// inline (exact fp32 linspace replication), the 8 rotation-invariant
// features, sampled/new_LOA outputs, g_gidx, and zeroes the stat buffers.
// ---------------------------------------------------------------------------
__global__ void __launch_bounds__(256) k_rif(const float* __restrict__ contour,
                                             const float* __restrict__ loa,
                                             float* __restrict__ out)
{
    const unsigned FULL = 0xffffffffu;
    int tid  = threadIdx.x;
    if (blockIdx.x == 0) {                       // zero stats (1024 doubles x2)
        #pragma unroll
        for (int j = 0; j < 4; ++j) {
            ((double*)g_sum)[tid + j*256] = 0.0;
            ((double*)g_sq )[tid + j*256] = 0.0;
        }
    }
    int w    = blockIdx.x * 8 + (tid >> 5);
    int lane = tid & 31;
    int b = w >> 11;           // S = 2048
    int s = w & (Sc - 1);

    int i0;
    if (s == Sc - 1) {
        i0 = Nn - 1;
    } else {
        // jnp.linspace: t = fl(s/2047); v = fl(8191*t); trunc to int32
        float t = __fdiv_rn((float)s, 2047.0f);
        float v = __fmul_rn(8191.0f, t);
        i0 = (int)v;
    }
    int n = (i0 - (Kc/2) + lane) & (Nn - 1);
    if (b == 0) g_gidx[s*Kc + lane] = n;

    const float* cp = contour + ((size_t)b*Nn + i0)*3;
    float spx = cp[0], spy = cp[1], spz = cp[2];
    const float* ap = loa + ((size_t)b*Nn + i0)*3;
    float ax = ap[0], ay = ap[1], az = ap[2];

    if (lane < 3) {
        out[(b*Sc + s)*3 + lane]           = cp[lane];
        out[Bc*Sc*3 + (b*Sc + s)*3 + lane] = ap[lane];
    }

    const float* pp_ = contour + ((size_t)b*Nn + n)*3;
    float lx = pp_[0] - spx, ly = pp_[1] - spy, lz = pp_[2] - spz;
    const float* lp = loa + ((size_t)b*Nn + n)*3;
    float nlx = lp[0], nly = lp[1], nlz = lp[2];

    float sq = lx*lx + ly*ly + lz*lz;
    float d1 = (sq > 0.f) ? sqrtf(sq) : 0.f;
    float inv = (d1 > 0.f) ? (1.f / d1) : 0.f;
    float ux = lx*inv, uy = ly*inv, uz = lz*inv;

    int pl = (lane + 31) & 31;   // k-1 (wrap)
    float plx = __shfl_sync(FULL, lx, pl);
    float ply = __shfl_sync(FULL, ly, pl);
    float plz = __shfl_sync(FULL, lz, pl);
    float pnlx = __shfl_sync(FULL, nlx, pl);
    float pnly = __shfl_sync(FULL, nly, pl);
    float pnlz = __shfl_sync(FULL, nlz, pl);
    float pux = __shfl_sync(FULL, ux, pl);
    float puy = __shfl_sync(FULL, uy, pl);
    float puz = __shfl_sync(FULL, uz, pl);

    float ivx = lx - plx, ivy = ly - ply, ivz = lz - plz;
    float isq = ivx*ivx + ivy*ivy + ivz*ivz;
    float idn = (isq > 0.f) ? sqrtf(isq) : 0.f;
    float ii  = (idn > 0.f) ? (1.f / idn) : 0.f;
    float iux = ivx*ii, iuy = ivy*ii, iuz = ivz*ii;

    float a1 = ux*ax + uy*ay + uz*az;
    float a2 = ux*nlx + uy*nly + uz*nlz;
    float a3 = acosf(clamp_ac(nlx*ax + nly*ay + nlz*az));
    float a4 = iux*nlx + iuy*nly + iuz*nlz;
    float a5 = iux*pnlx + iuy*pnly + iuz*pnlz;
    float a6 = acosf(clamp_ac(nlx*pnlx + nly*pnly + nlz*pnlz));
    float d2 = acosf(clamp_ac(ux*pux + uy*puy + uz*puz));

    size_t p = (size_t)(b*Sc + s)*Kc + lane;
    g_X0[0*(size_t)PP + p] = d1;
    g_X0[1*(size_t)PP + p] = d2;
    g_X0[2*(size_t)PP + p] = a1;
    g_X0[3*(size_t)PP + p] = a2;
    g_X0[4*(size_t)PP + p] = a3;
    g_X0[5*(size_t)PP + p] = a4;
    g_X0[6*(size_t)PP + p] = a5;
    g_X0[7*(size_t)PP + p] = a6;
}

// ---------------------------------------------------------------------------
// Fused conv(1x1) + batch-stat accumulation, register-tiled SGEMM.
// Block = TILE_O out-channels x 128 positions, 256 threads (16x16).
// Thread microtile: OW = TILE_O/16 outputs x 8 positions.
// MODE 0 = raw input, MODE 1 = BN+ReLU of previous layer,
// MODE 2 = ch<64 BN+ReLU(Y2), ch 64..127 gathered from feature_maps.
// LAYER 3 epilogue reduces per-k-group max/min instead of storing Y.
// ---------------------------------------------------------------------------
template<int CIN, int COUT, int TILE_O, int MODE, int LAYER>
__global__ void __launch_bounds__(256) k_conv(const float* __restrict__ W,
                                              const float* __restrict__ bias,
                                              const float* __restrict__ fmaps)
{
    constexpr int OW = TILE_O / 16;
    constexpr int PL = (LAYER > 0) ? (LAYER - 1) : 0;

    const float* Xin;
    float* Yout;
    if      (LAYER == 0) { Xin = g_X0; Yout = g_Y1; }
    else if (LAYER == 1) { Xin = g_Y1; Yout = g_Y2; }
    else if (LAYER == 2) { Xin = g_Y2; Yout = g_Y3; }
    else                 { Xin = g_Y3; Yout = nullptr; }

    __shared__ __align__(16) float sW[8][TILE_O];
    __shared__ __align__(16) float sX[8][128];
    __shared__ float sSc[CIN];
    __shared__ float sSh[CIN];
    __shared__ int   sN[128];

    int tid = threadIdx.x;
    int o0  = blockIdx.y * TILE_O;
    int p0  = blockIdx.x * 128;
    int bb  = p0 >> 16;                 // 65536 positions per batch

    if (MODE >= 1) {
        if (tid < CIN) { sSc[tid] = g_scale[PL][tid]; sSh[tid] = g_shift[PL][tid]; }
    }
    if (MODE == 2) {
        if (tid < 128) sN[tid] = g_gidx[(p0 & 65535) + tid];
    }
    __syncthreads();   // sSc/sSh/sN visible to all threads before mainloop reads

    int tx = tid & 15, ty = tid >> 4;
    int kcl = tid >> 5;          // 0..7  (X-fill channel)
    int pp4 = (tid & 31) * 4;    // 0..124 (X-fill position, float4)

    float acc[OW][8];
    #pragma unroll
    for (int i = 0; i < OW; ++i)
        #pragma unroll
        for (int j = 0; j < 8; ++j) acc[i][j] = 0.f;

    #pragma unroll 1
    for (int cc = 0; cc < CIN/8; ++cc) {
        int c0 = cc * 8;
        // weights: sW[c][o]  (transposed for vector loads in compute)
        for (int idx = tid; idx < TILE_O*8; idx += 256) {
            int o = idx & (TILE_O - 1), c = idx / TILE_O;
            sW[c][o] = W[(o0 + o)*CIN + c0 + c];
        }
        // X: one float4 per thread
        {
            int c = c0 + kcl;
            float4 v;
            if (MODE == 0) {
                v = *(const float4*)&Xin[(size_t)c*PP + p0 + pp4];
            } else if (MODE == 1 || (MODE == 2 && c0 + kcl < 64)) {
                float4 r = *(const float4*)&Xin[(size_t)c*PP + p0 + pp4];
                float scv = sSc[c], shv = sSh[c];
                v.x = fmaxf(fmaf(r.x, scv, shv), 0.f);
                v.y = fmaxf(fmaf(r.y, scv, shv), 0.f);
                v.z = fmaxf(fmaf(r.z, scv, shv), 0.f);
                v.w = fmaxf(fmaf(r.w, scv, shv), 0.f);
            } else {
                const float* fp = fmaps + ((size_t)bb*Dc + (c - 64))*Nn;
                v.x = fp[sN[pp4 + 0]];
                v.y = fp[sN[pp4 + 1]];
                v.z = fp[sN[pp4 + 2]];
                v.w = fp[sN[pp4 + 3]];
            }
            *(float4*)&sX[kcl][pp4] = v;
        }
        __syncthreads();

        #pragma unroll
        for (int kc = 0; kc < 8; ++kc) {
            float4 xa = ((const float4*)sX[kc])[tx*2];
            float4 xb = ((const float4*)sX[kc])[tx*2 + 1];
            float xr[8] = {xa.x, xa.y, xa.z, xa.w, xb.x, xb.y, xb.z, xb.w};
            float wr[OW];
            if constexpr (OW == 8) {
                float4 wa = ((const float4*)sW[kc])[ty*2];
                float4 wb = ((const float4*)sW[kc])[ty*2 + 1];
                wr[0]=wa.x; wr[1]=wa.y; wr[2]=wa.z; wr[3]=wa.w;
                wr[4]=wb.x; wr[5]=wb.y; wr[6]=wb.z; wr[7]=wb.w;
            } else if constexpr (OW == 4) {
                float4 wa = ((const float4*)sW[kc])[ty];
                wr[0]=wa.x; wr[1]=wa.y; wr[2]=wa.z; wr[3]=wa.w;
            } else {
                #pragma unroll
                for (int i = 0; i < OW; ++i) wr[i] = sW[kc][ty*OW + i];
            }
            #pragma unroll
            for (int i = 0; i < OW; ++i)
                #pragma unroll
                for (int j = 0; j < 8; ++j)
                    acc[i][j] = fmaf(wr[i], xr[j], acc[i][j]);
        }
        __syncthreads();
    }

    // epilogue: bias; store Y (layers 0-2) or k-group max/min (layer 3);
    // accumulate per-channel sum / sumsq.
    #pragma unroll
    for (int i = 0; i < OW; ++i) {
        int o = o0 + ty*OW + i;
        float bo = bias[o];
        float y[8];
        #pragma unroll
        for (int j = 0; j < 8; ++j) y[j] = acc[i][j] + bo;

        if (LAYER < 3) {
            *(float4*)&Yout[(size_t)o*PP + p0 + tx*8]     = make_float4(y[0], y[1], y[2], y[3]);
            *(float4*)&Yout[(size_t)o*PP + p0 + tx*8 + 4] = make_float4(y[4], y[5], y[6], y[7]);
        } else {
            float mx = y[0], mn = y[0];
            #pragma unroll
            for (int j = 1; j < 8; ++j) { mx = fmaxf(mx, y[j]); mn = fminf(mn, y[j]); }
            // combine 4 tx-lanes covering one 32-position k-group
            #pragma unroll
            for (int off = 1; off <= 2; off <<= 1) {
                mx = fmaxf(mx, __shfl_xor_sync(0xffffffffu, mx, off));
                mn = fminf(mn, __shfl_xor_sync(0xffffffffu, mn, off));
            }
            if ((tx & 3) == 0) {
                int grp = (p0 >> 5) + (tx >> 2);
                g_mx[(size_t)o*NG + grp] = mx;
                g_mn[(size_t)o*NG + grp] = mn;
            }
        }

        float s1 = 0.f, s2 = 0.f;
        #pragma unroll
        for (int j = 0; j < 8; ++j) { s1 += y[j]; s2 += y[j]*y[j]; }
        #pragma unroll
        for (int off = 1; off <= 8; off <<= 1) {
            s1 += __shfl_xor_sync(0xffffffffu, s1, off);
            s2 += __shfl_xor_sync(0xffffffffu, s2, off);
        }
        if (tx == 0) {
            atomicAdd(&g_sum[LAYER][o], (double)s1);
            atomicAdd(&g_sq [LAYER][o], (double)s2);
        }
    }
}

// ---------------------------------------------------------------------------
__global__ void k_finalize(int layer, const float* __restrict__ gamma,
                           const float* __restrict__ beta, int cout)
{
    int c = threadIdx.x;
    if (c < cout) {
        double mean = g_sum[layer][c] / (double)PP;
        double var  = g_sq [layer][c] / (double)PP - mean*mean;
        double invs = rsqrt(var + 1e-5);
        double sc   = (double)gamma[c] * invs;
        g_scale[layer][c] = (float)sc;
        g_shift[layer][c] = (float)((double)beta[c] - mean * sc);
    }
}

// ---------------------------------------------------------------------------
// k_out: out[(b*256+o)*S + s] = relu(sc>0 ? sc*mx+sh : sc*mn+sh)
// ---------------------------------------------------------------------------
__global__ void __launch_bounds__(256) k_out(float* __restrict__ out)
{
    int t = blockIdx.x * blockDim.x + threadIdx.x;   // over 8*256*2048
    if (t >= Bc*256*Sc) return;
    int s = t & (Sc - 1);
    int o = (t >> 11) & 255;
    int b = t >> 19;
    float sc = g_scale[3][o], sh = g_shift[3][o];
    int grp = b*Sc + s;
    float v = (sc > 0.f) ? g_mx[(size_t)o*NG + grp] : g_mn[(size_t)o*NG + grp];
    out[2*Bc*Sc*3 + t] = fmaxf(fmaf(v, sc, sh), 0.f);
}

// ---------------------------------------------------------------------------
extern "C" void kernel_launch(void* const* d_in, const int* in_sizes, int n_in,
                              void* d_out, int out_size)
{
    const float* contour = (const float*)d_in[0];
    const float* loa     = (const float*)d_in[1];
    const float* fmaps   = (const float*)d_in[2];
    const float* fe_w1   = (const float*)d_in[3];
    const float* fe_b1   = (const float*)d_in[4];
    const float* fe_g1   = (const float*)d_in[5];
    const float* fe_be1  = (const float*)d_in[6];
    const float* fe_w2   = (const float*)d_in[7];
    const float* fe_b2   = (const float*)d_in[8];
    const float* fe_g2   = (const float*)d_in[9];
    const float* fe_be2  = (const float*)d_in[10];
    const float* fl_w1   = (const float*)d_in[11];
    const float* fl_b1   = (const float*)d_in[12];
    const float* fl_g1   = (const float*)d_in[13];
    const float* fl_be1  = (const float*)d_in[14];
    const float* fl_w2   = (const float*)d_in[15];
    const float* fl_b2   = (const float*)d_in[16];
    const float* fl_g2   = (const float*)d_in[17];
    const float* fl_be2  = (const float*)d_in[18];
    float* out = (float*)d_out;

    const int PBLK = PP / 128;   // 4096

    k_rif<<<Bc*Sc/8, 256>>>(contour, loa, out);                       // launch 0

    k_conv<8,   32,  32, 0, 0><<<dim3(PBLK, 1), 256>>>(fe_w1, fe_b1, nullptr);  // 1
    k_finalize<<<1, 256>>>(0, fe_g1, fe_be1, 32);                               // 2

    k_conv<32,  64,  64, 1, 1><<<dim3(PBLK, 1), 256>>>(fe_w2, fe_b2, nullptr);  // 3
    k_finalize<<<1, 256>>>(1, fe_g2, fe_be2, 64);                               // 4

    k_conv<128, 128, 128, 2, 2><<<dim3(PBLK, 1), 256>>>(fl_w1, fl_b1, fmaps);   // 5 (ncu)
    k_finalize<<<1, 256>>>(2, fl_g1, fl_be1, 128);                              // 6

    k_conv<128, 256, 128, 1, 3><<<dim3(PBLK, 2), 256>>>(fl_w2, fl_b2, nullptr); // 7
    k_finalize<<<1, 256>>>(3, fl_g2, fl_be2, 256);                              // 8

    k_out<<<(Bc*256*Sc + 255)/256, 256>>>(out);                                 // 9
}

// round 10
// speedup vs baseline: 3.8732x; 2.2110x over previous
#include <cuda_runtime.h>
#include <cuda_bf16.h>
#include <math.h>
#include <stdint.h>

#define Bc 8
#define Nn 8192
#define Sc 2048
#define Kc 32
#define Dc 64
#define PP (Bc*Sc*Kc)   // 524288 positions
#define NG (PP/32)      // 16384 k-groups

// ---------------- scratch ---------------------------------------------------
__device__ float g_X0[8   * PP];
__device__ float g_Y1[32  * PP];
__device__ float g_Y2[64  * PP];
__device__ float g_Y3[128 * PP];
__device__ float g_mx[256 * NG];
__device__ float g_mn[256 * NG];
__device__ int   g_gidx[Sc*Kc];
__device__ double g_sum[4][256];
__device__ double g_sq [4][256];
__device__ float g_scale[4][256];
__device__ float g_shift[4][256];

__device__ __forceinline__ float clamp_ac(float x) {
    return fminf(fmaxf(x, -0.9999999f), 0.9999999f);
}

// =================== warp MMA helpers (baseline PTX, no sm_103a) ===========
__device__ __forceinline__ uint32_t smem_u32(const void* p) {
    uint32_t a;
    asm("{ .reg .u64 t; cvta.to.shared.u64 t, %1; cvt.u32.u64 %0, t; }"
        : "=r"(a) : "l"(p));
    return a;
}
__device__ __forceinline__ void ldsm4(uint32_t* r, uint32_t a) {
    asm volatile("ldmatrix.sync.aligned.m8n8.x4.shared.b16 {%0,%1,%2,%3}, [%4];"
        : "=r"(r[0]), "=r"(r[1]), "=r"(r[2]), "=r"(r[3]) : "r"(a));
}
__device__ __forceinline__ void ldsm4t(uint32_t* r, uint32_t a) {
    asm volatile("ldmatrix.sync.aligned.m8n8.x4.trans.shared.b16 {%0,%1,%2,%3}, [%4];"
        : "=r"(r[0]), "=r"(r[1]), "=r"(r[2]), "=r"(r[3]) : "r"(a));
}
__device__ __forceinline__ void mma_bf16(float* d, const uint32_t* a, const uint32_t* b) {
    asm volatile("mma.sync.aligned.m16n8k16.row.col.f32.bf16.bf16.f32 "
        "{%0,%1,%2,%3}, {%4,%5,%6,%7}, {%8,%9}, {%0,%1,%2,%3};"
        : "+f"(d[0]), "+f"(d[1]), "+f"(d[2]), "+f"(d[3])
        : "r"(a[0]), "r"(a[1]), "r"(a[2]), "r"(a[3]), "r"(b[0]), "r"(b[1]));
}
__device__ __forceinline__ uint32_t pack_hi2(float a, float b, float& ra, float& rb) {
    __nv_bfloat16 ha = __float2bfloat16_rn(a), hb = __float2bfloat16_rn(b);
    ra = a - __bfloat162float(ha);
    rb = b - __bfloat162float(hb);
    return (uint32_t)__bfloat16_as_ushort(ha) | ((uint32_t)__bfloat16_as_ushort(hb) << 16);
}
__device__ __forceinline__ uint32_t pack2(float a, float b) {
    return (uint32_t)__bfloat16_as_ushort(__float2bfloat16_rn(a))
         | ((uint32_t)__bfloat16_as_ushort(__float2bfloat16_rn(b)) << 16);
}

// ---------------------------------------------------------------------------
// k_rif: unchanged (passing since R5).
// ---------------------------------------------------------------------------
__global__ void __launch_bounds__(256) k_rif(const float* __restrict__ contour,
                                             const float* __restrict__ loa,
                                             float* __restrict__ out)
{
    const unsigned FULL = 0xffffffffu;
    int tid  = threadIdx.x;
    if (blockIdx.x == 0) {
        #pragma unroll
        for (int j = 0; j < 4; ++j) {
            ((double*)g_sum)[tid + j*256] = 0.0;
            ((double*)g_sq )[tid + j*256] = 0.0;
        }
    }
    int w    = blockIdx.x * 8 + (tid >> 5);
    int lane = tid & 31;
    int b = w >> 11;
    int s = w & (Sc - 1);

    int i0;
    if (s == Sc - 1) i0 = Nn - 1;
    else {
        float t = __fdiv_rn((float)s, 2047.0f);
        float v = __fmul_rn(8191.0f, t);
        i0 = (int)v;
    }
    int n = (i0 - (Kc/2) + lane) & (Nn - 1);
    if (b == 0) g_gidx[s*Kc + lane] = n;

    const float* cp = contour + ((size_t)b*Nn + i0)*3;
    float spx = cp[0], spy = cp[1], spz = cp[2];
    const float* ap = loa + ((size_t)b*Nn + i0)*3;
    float ax = ap[0], ay = ap[1], az = ap[2];

    if (lane < 3) {
        out[(b*Sc + s)*3 + lane]           = cp[lane];
        out[Bc*Sc*3 + (b*Sc + s)*3 + lane] = ap[lane];
    }

    const float* pp_ = contour + ((size_t)b*Nn + n)*3;
    float lx = pp_[0] - spx, ly = pp_[1] - spy, lz = pp_[2] - spz;
    const float* lp = loa + ((size_t)b*Nn + n)*3;
    float nlx = lp[0], nly = lp[1], nlz = lp[2];

    float sq = lx*lx + ly*ly + lz*lz;
    float d1 = (sq > 0.f) ? sqrtf(sq) : 0.f;
    float inv = (d1 > 0.f) ? (1.f / d1) : 0.f;
    float ux = lx*inv, uy = ly*inv, uz = lz*inv;

    int pl = (lane + 31) & 31;
    float plx = __shfl_sync(FULL, lx, pl);
    float ply = __shfl_sync(FULL, ly, pl);
    float plz = __shfl_sync(FULL, lz, pl);
    float pnlx = __shfl_sync(FULL, nlx, pl);
    float pnly = __shfl_sync(FULL, nly, pl);
    float pnlz = __shfl_sync(FULL, nlz, pl);
    float pux = __shfl_sync(FULL, ux, pl);
    float puy = __shfl_sync(FULL, uy, pl);
    float puz = __shfl_sync(FULL, uz, pl);

    float ivx = lx - plx, ivy = ly - ply, ivz = lz - plz;
    float isq = ivx*ivx + ivy*ivy + ivz*ivz;
    float idn = (isq > 0.f) ? sqrtf(isq) : 0.f;
    float ii  = (idn > 0.f) ? (1.f / idn) : 0.f;
    float iux = ivx*ii, iuy = ivy*ii, iuz = ivz*ii;

    float a1 = ux*ax + uy*ay + uz*az;
    float a2 = ux*nlx + uy*nly + uz*nlz;
    float a3 = acosf(clamp_ac(nlx*ax + nly*ay + nlz*az));
    float a4 = iux*nlx + iuy*nly + iuz*nlz;
    float a5 = iux*pnlx + iuy*pnly + iuz*pnlz;
    float a6 = acosf(clamp_ac(nlx*pnlx + nly*pnly + nlz*pnlz));
    float d2 = acosf(clamp_ac(ux*pux + uy*puy + uz*puz));

    size_t p = (size_t)(b*Sc + s)*Kc + lane;
    g_X0[0*(size_t)PP + p] = d1;
    g_X0[1*(size_t)PP + p] = d2;
    g_X0[2*(size_t)PP + p] = a1;
    g_X0[3*(size_t)PP + p] = a2;
    g_X0[4*(size_t)PP + p] = a3;
    g_X0[5*(size_t)PP + p] = a4;
    g_X0[6*(size_t)PP + p] = a5;
    g_X0[7*(size_t)PP + p] = a6;
}

// ---------------------------------------------------------------------------
// FFMA conv for small layers 0 (8->32) and 1 (32->64). Unchanged (passing).
// ---------------------------------------------------------------------------
template<int CIN, int COUT, int TILE_O, int MODE, int LAYER>
__global__ void __launch_bounds__(256) k_conv(const float* __restrict__ W,
                                              const float* __restrict__ bias)
{
    constexpr int OW = TILE_O / 16;
    constexpr int PL = (LAYER > 0) ? (LAYER - 1) : 0;

    const float* Xin  = (LAYER == 0) ? g_X0 : g_Y1;
    float*       Yout = (LAYER == 0) ? g_Y1 : g_Y2;

    __shared__ __align__(16) float sW[8][TILE_O];
    __shared__ __align__(16) float sX[8][128];
    __shared__ float sSc[CIN];
    __shared__ float sSh[CIN];

    int tid = threadIdx.x;
    int o0  = blockIdx.y * TILE_O;
    int p0  = blockIdx.x * 128;

    if (MODE >= 1) {
        if (tid < CIN) { sSc[tid] = g_scale[PL][tid]; sSh[tid] = g_shift[PL][tid]; }
    }
    __syncthreads();

    int tx = tid & 15, ty = tid >> 4;
    int kcl = tid >> 5;
    int pp4 = (tid & 31) * 4;

    float acc[OW][8];
    #pragma unroll
    for (int i = 0; i < OW; ++i)
        #pragma unroll
        for (int j = 0; j < 8; ++j) acc[i][j] = 0.f;

    #pragma unroll 1
    for (int cc = 0; cc < CIN/8; ++cc) {
        int c0 = cc * 8;
        for (int idx = tid; idx < TILE_O*8; idx += 256) {
            int o = idx & (TILE_O - 1), c = idx / TILE_O;
            sW[c][o] = W[(o0 + o)*CIN + c0 + c];
        }
        {
            int c = c0 + kcl;
            float4 v;
            if (MODE == 0) {
                v = *(const float4*)&Xin[(size_t)c*PP + p0 + pp4];
            } else {
                float4 r = *(const float4*)&Xin[(size_t)c*PP + p0 + pp4];
                float scv = sSc[c], shv = sSh[c];
                v.x = fmaxf(fmaf(r.x, scv, shv), 0.f);
                v.y = fmaxf(fmaf(r.y, scv, shv), 0.f);
                v.z = fmaxf(fmaf(r.z, scv, shv), 0.f);
                v.w = fmaxf(fmaf(r.w, scv, shv), 0.f);
            }
            *(float4*)&sX[kcl][pp4] = v;
        }
        __syncthreads();

        #pragma unroll
        for (int kc = 0; kc < 8; ++kc) {
            float4 xa = ((const float4*)sX[kc])[tx*2];
            float4 xb = ((const float4*)sX[kc])[tx*2 + 1];
            float xr[8] = {xa.x, xa.y, xa.z, xa.w, xb.x, xb.y, xb.z, xb.w};
            float wr[OW];
            if constexpr (OW == 4) {
                float4 wa = ((const float4*)sW[kc])[ty];
                wr[0]=wa.x; wr[1]=wa.y; wr[2]=wa.z; wr[3]=wa.w;
            } else {
                #pragma unroll
                for (int i = 0; i < OW; ++i) wr[i] = sW[kc][ty*OW + i];
            }
            #pragma unroll
            for (int i = 0; i < OW; ++i)
                #pragma unroll
                for (int j = 0; j < 8; ++j)
                    acc[i][j] = fmaf(wr[i], xr[j], acc[i][j]);
        }
        __syncthreads();
    }

    #pragma unroll
    for (int i = 0; i < OW; ++i) {
        int o = o0 + ty*OW + i;
        float bo = bias[o];
        float y[8];
        #pragma unroll
        for (int j = 0; j < 8; ++j) y[j] = acc[i][j] + bo;

        *(float4*)&Yout[(size_t)o*PP + p0 + tx*8]     = make_float4(y[0], y[1], y[2], y[3]);
        *(float4*)&Yout[(size_t)o*PP + p0 + tx*8 + 4] = make_float4(y[4], y[5], y[6], y[7]);

        float s1 = 0.f, s2 = 0.f;
        #pragma unroll
        for (int j = 0; j < 8; ++j) { s1 += y[j]; s2 += y[j]*y[j]; }
        #pragma unroll
        for (int off = 1; off <= 8; off <<= 1) {
            s1 += __shfl_xor_sync(0xffffffffu, s1, off);
            s2 += __shfl_xor_sync(0xffffffffu, s2, off);
        }
        if (tx == 0) {
            atomicAdd(&g_sum[LAYER][o], (double)s1);
            atomicAdd(&g_sq [LAYER][o], (double)s2);
        }
    }
}

// ===========================================================================
// h_fl1: warp-MMA bf16-split GEMM, layer 2 (128ch -> 128ch), N-tile = 128.
// smem: Xh@0 Xl@32K Wh@64K Wl@96K misc@128K.  512 thr, warps 4(m)x4(n).
// Swizzle: 16B granule index ^ (row&7).
// ===========================================================================
#define FL1_SMEM (131072 + 1024)
__global__ void __launch_bounds__(512) h_fl1(const float* __restrict__ W,
                                             const float* __restrict__ bias,
                                             const float* __restrict__ fmaps)
{
    extern __shared__ char smem[];
    const uint32_t XH = 0, XL = 32768, WH = 65536, WL = 98304, MISC = 131072;
    float* sSc = (float*)(smem + MISC);
    float* sSh = (float*)(smem + MISC + 256);
    int*   sG  = (int*)  (smem + MISC + 512);
    uint32_t sb = smem_u32(smem);

    int tid = threadIdx.x, lane = tid & 31, wid = tid >> 5;
    int wm = wid & 3, wn = wid >> 2;           // warp tile: rows wm*32, cols wn*32

    if (tid < 64) { sSc[tid] = g_scale[1][tid]; sSh[tid] = g_shift[1][tid]; }

    // W -> smem bf16 hi/lo, swizzled rows of 256B
    {
        int o = tid >> 2, c0 = (tid & 3) * 32;
        const float* wr = W + o*128 + c0;
        uint32_t rowb = (uint32_t)o * 256;
        #pragma unroll
        for (int j = 0; j < 16; ++j) {
            int c = c0 + 2*j;
            float ra, rb;
            uint32_t hi = pack_hi2(wr[2*j], wr[2*j+1], ra, rb);
            uint32_t lo = pack2(ra, rb);
            uint32_t byt = rowb + ((((c >> 3) ^ (o & 7)) & 15) << 4) + (c & 7)*2;
            *(uint32_t*)(smem + WH + byt) = hi;
            *(uint32_t*)(smem + WL + byt) = lo;
        }
    }

    int r0 = wm*32 + (lane >> 2);
    float bs[4] = { bias[r0], bias[r0 + 8], bias[r0 + 16], bias[r0 + 24] };
    double d1a[4] = {0,0,0,0}, d2a[4] = {0,0,0,0};
    __syncthreads();

    for (int tile = blockIdx.x; tile < PP/128; tile += gridDim.x) {
        int p0 = tile * 128, bb = p0 >> 16;
        __syncthreads();                       // prev tile's ldmatrix done
        if (tid < 128) sG[tid] = g_gidx[(p0 & 65535) + tid];
        __syncthreads();

        // fill X (bn_relu(Y2) for c<64, fmaps gather for c>=64), hi/lo
        {
            int c = tid >> 2, n0 = (tid & 3) * 32;
            float v[32];
            if (c < 64) {
                const float4* src = (const float4*)&g_Y2[(size_t)c*PP + p0 + n0];
                float scv = sSc[c], shv = sSh[c];
                #pragma unroll
                for (int j = 0; j < 8; ++j) {
                    float4 r = src[j];
                    v[4*j+0] = fmaxf(fmaf(r.x, scv, shv), 0.f);
                    v[4*j+1] = fmaxf(fmaf(r.y, scv, shv), 0.f);
                    v[4*j+2] = fmaxf(fmaf(r.z, scv, shv), 0.f);
                    v[4*j+3] = fmaxf(fmaf(r.w, scv, shv), 0.f);
                }
            } else {
                const float* fp = fmaps + ((size_t)bb*Dc + (c - 64))*Nn;
                #pragma unroll
                for (int j = 0; j < 32; ++j) v[j] = fp[sG[n0 + j]];
            }
            uint32_t rowb = (uint32_t)c * 256;
            #pragma unroll
            for (int j = 0; j < 16; ++j) {
                int n = n0 + 2*j;
                float ra, rb;
                uint32_t hi = pack_hi2(v[2*j], v[2*j+1], ra, rb);
                uint32_t lo = pack2(ra, rb);
                uint32_t byt = rowb + ((((n >> 3) ^ (c & 7)) & 15) << 4) + (n & 7)*2;
                *(uint32_t*)(smem + XH + byt) = hi;
                *(uint32_t*)(smem + XL + byt) = lo;
            }
        }
        __syncthreads();

        float acc[2][4][4];
        #pragma unroll
        for (int i = 0; i < 2; ++i)
            #pragma unroll
            for (int j = 0; j < 4; ++j)
                #pragma unroll
                for (int q = 0; q < 4; ++q) acc[i][j][q] = 0.f;

        #pragma unroll
        for (int s = 0; s < 8; ++s) {
            uint32_t Ah[8], Al[8], Bh[8], Bl[8];
            #pragma unroll
            for (int mf = 0; mf < 2; ++mf) {
                int rr = wm*32 + mf*16 + (lane & 15);
                uint32_t g = (uint32_t)(2*s + (lane >> 4));
                uint32_t byt = (uint32_t)rr*256 + (((g ^ (rr & 7)) & 15) << 4);
                ldsm4(Ah + mf*4, sb + WH + byt);
                ldsm4(Al + mf*4, sb + WL + byt);
            }
            #pragma unroll
            for (int half = 0; half < 2; ++half) {
                int ti = lane >> 3;
                int k = s*16 + (ti & 1)*8 + (lane & 7);
                int ng = ((wn*32 + half*16) >> 3) + (ti >> 1);
                uint32_t byt = (uint32_t)k*256 + (((ng ^ (k & 7)) & 15) << 4);
                ldsm4t(Bh + half*4, sb + XH + byt);
                ldsm4t(Bl + half*4, sb + XL + byt);
            }
            #pragma unroll
            for (int mf = 0; mf < 2; ++mf)
                #pragma unroll
                for (int nf = 0; nf < 4; ++nf) {
                    mma_bf16(acc[mf][nf], Ah + mf*4, Bh + nf*2);
                    mma_bf16(acc[mf][nf], Al + mf*4, Bh + nf*2);
                    mma_bf16(acc[mf][nf], Ah + mf*4, Bl + nf*2);
                }
        }

        // epilogue: bias, store Y3, stats
        #pragma unroll
        for (int mf = 0; mf < 2; ++mf) {
            int r = wm*32 + mf*16 + (lane >> 2);
            float b0 = bs[mf*2], b1 = bs[mf*2 + 1];
            float s10 = 0.f, s20 = 0.f, s11 = 0.f, s21 = 0.f;
            #pragma unroll
            for (int nf = 0; nf < 4; ++nf) {
                int col = p0 + wn*32 + nf*8 + 2*(lane & 3);
                float y0 = acc[mf][nf][0] + b0, y1 = acc[mf][nf][1] + b0;
                float y2 = acc[mf][nf][2] + b1, y3 = acc[mf][nf][3] + b1;
                *(float2*)&g_Y3[(size_t)r*PP + col]       = make_float2(y0, y1);
                *(float2*)&g_Y3[(size_t)(r + 8)*PP + col] = make_float2(y2, y3);
                s10 += y0 + y1; s20 += y0*y0 + y1*y1;
                s11 += y2 + y3; s21 += y2*y2 + y3*y3;
            }
            #pragma unroll
            for (int off = 1; off <= 2; off <<= 1) {
                s10 += __shfl_xor_sync(0xffffffffu, s10, off);
                s20 += __shfl_xor_sync(0xffffffffu, s20, off);
                s11 += __shfl_xor_sync(0xffffffffu, s11, off);
                s21 += __shfl_xor_sync(0xffffffffu, s21, off);
            }
            if ((lane & 3) == 0) {
                d1a[mf*2]   += (double)s10; d2a[mf*2]   += (double)s20;
                d1a[mf*2+1] += (double)s11; d2a[mf*2+1] += (double)s21;
            }
        }
    }

    if ((lane & 3) == 0) {
        #pragma unroll
        for (int q = 0; q < 4; ++q) {
            int r = wm*32 + (q >> 1)*16 + (q & 1)*8 + (lane >> 2);
            atomicAdd(&g_sum[2][r], d1a[q]);
            atomicAdd(&g_sq [2][r], d2a[q]);
        }
    }
}

// ===========================================================================
// h_fl2: warp-MMA bf16-split GEMM, layer 3 (128ch -> 256ch), N-tile = 64.
// smem: Xh@0 Xl@16K Wh@32K Wl@96K misc@160K.  512 thr, warps 8(m)x2(n).
// Epilogue: per-lane k-group max/min (warp n-range == one 32-pos group).
// ===========================================================================
#define FL2_SMEM (163840 + 1024)
__global__ void __launch_bounds__(512) h_fl2(const float* __restrict__ W,
                                             const float* __restrict__ bias)
{
    extern __shared__ char smem[];
    const uint32_t XH = 0, XL = 16384, WH = 32768, WL = 98304, MISC = 163840;
    float* sSc = (float*)(smem + MISC);
    float* sSh = (float*)(smem + MISC + 512);
    uint32_t sb = smem_u32(smem);

    int tid = threadIdx.x, lane = tid & 31, wid = tid >> 5;
    int wm = wid >> 1, wn = wid & 1;           // rows wm*32, cols wn*32

    if (tid < 128) { sSc[tid] = g_scale[2][tid]; sSh[tid] = g_shift[2][tid]; }

    // W2 (256x128) -> smem bf16 hi/lo
    {
        int o = tid >> 1, c0 = (tid & 1) * 64;
        const float* wr = W + o*128 + c0;
        uint32_t rowb = (uint32_t)o * 256;
        #pragma unroll
        for (int j = 0; j < 32; ++j) {
            int c = c0 + 2*j;
            float ra, rb;
            uint32_t hi = pack_hi2(wr[2*j], wr[2*j+1], ra, rb);
            uint32_t lo = pack2(ra, rb);
            uint32_t byt = rowb + ((((c >> 3) ^ (o & 7)) & 15) << 4) + (c & 7)*2;
            *(uint32_t*)(smem + WH + byt) = hi;
            *(uint32_t*)(smem + WL + byt) = lo;
        }
    }

    int r0 = wm*32 + (lane >> 2);
    float bs[4] = { bias[r0], bias[r0 + 8], bias[r0 + 16], bias[r0 + 24] };
    double d1a[4] = {0,0,0,0}, d2a[4] = {0,0,0,0};
    __syncthreads();

    for (int tile = blockIdx.x; tile < PP/64; tile += gridDim.x) {
        int p0 = tile * 64;
        __syncthreads();

        // fill X = bn_relu(Y3), rows 128B (64 pos)
        {
            int c = tid >> 2, n0 = (tid & 3) * 16;
            const float4* src = (const float4*)&g_Y3[(size_t)c*PP + p0 + n0];
            float scv = sSc[c], shv = sSh[c];
            uint32_t rowb = (uint32_t)c * 128;
            #pragma unroll
            for (int j = 0; j < 4; ++j) {
                float4 r = src[j];
                float v0 = fmaxf(fmaf(r.x, scv, shv), 0.f);
                float v1 = fmaxf(fmaf(r.y, scv, shv), 0.f);
                float v2 = fmaxf(fmaf(r.z, scv, shv), 0.f);
                float v3 = fmaxf(fmaf(r.w, scv, shv), 0.f);
                int n = n0 + 4*j;
                float ra, rb;
                uint32_t h0 = pack_hi2(v0, v1, ra, rb);
                uint32_t l0 = pack2(ra, rb);
                uint32_t h1 = pack_hi2(v2, v3, ra, rb);
                uint32_t l1 = pack2(ra, rb);
                uint32_t by0 = rowb + ((((n >> 3) ^ (c & 7)) & 7) << 4) + (n & 7)*2;
                int n2 = n + 2;
                uint32_t by1 = rowb + ((((n2 >> 3) ^ (c & 7)) & 7) << 4) + (n2 & 7)*2;
                *(uint32_t*)(smem + XH + by0) = h0;
                *(uint32_t*)(smem + XL + by0) = l0;
                *(uint32_t*)(smem + XH + by1) = h1;
                *(uint32_t*)(smem + XL + by1) = l1;
            }
        }
        __syncthreads();

        float acc[2][4][4];
        #pragma unroll
        for (int i = 0; i < 2; ++i)
            #pragma unroll
            for (int j = 0; j < 4; ++j)
                #pragma unroll
                for (int q = 0; q < 4; ++q) acc[i][j][q] = 0.f;

        #pragma unroll
        for (int s = 0; s < 8; ++s) {
            uint32_t Ah[8], Al[8], Bh[8], Bl[8];
            #pragma unroll
            for (int mf = 0; mf < 2; ++mf) {
                int rr = wm*32 + mf*16 + (lane & 15);
                uint32_t g = (uint32_t)(2*s + (lane >> 4));
                uint32_t byt = (uint32_t)rr*256 + (((g ^ (rr & 7)) & 15) << 4);
                ldsm4(Ah + mf*4, sb + WH + byt);
                ldsm4(Al + mf*4, sb + WL + byt);
            }
            #pragma unroll
            for (int half = 0; half < 2; ++half) {
                int ti = lane >> 3;
                int k = s*16 + (ti & 1)*8 + (lane & 7);
                int ng = ((wn*32 + half*16) >> 3) + (ti >> 1);
                uint32_t byt = (uint32_t)k*128 + (((ng ^ (k & 7)) & 7) << 4);
                ldsm4t(Bh + half*4, sb + XH + byt);
                ldsm4t(Bl + half*4, sb + XL + byt);
            }
            #pragma unroll
            for (int mf = 0; mf < 2; ++mf)
                #pragma unroll
                for (int nf = 0; nf < 4; ++nf) {
                    mma_bf16(acc[mf][nf], Ah + mf*4, Bh + nf*2);
                    mma_bf16(acc[mf][nf], Al + mf*4, Bh + nf*2);
                    mma_bf16(acc[mf][nf], Ah + mf*4, Bl + nf*2);
                }
        }

        // epilogue: k-group max/min + stats (no Y4 store)
        int grp = tile*2 + wn;
        #pragma unroll
        for (int mf = 0; mf < 2; ++mf) {
            int r = wm*32 + mf*16 + (lane >> 2);
            float b0 = bs[mf*2], b1 = bs[mf*2 + 1];
            float mx0 = -1e30f, mn0 = 1e30f, mx1 = -1e30f, mn1 = 1e30f;
            float s10 = 0.f, s20 = 0.f, s11 = 0.f, s21 = 0.f;
            #pragma unroll
            for (int nf = 0; nf < 4; ++nf) {
                float y0 = acc[mf][nf][0] + b0, y1 = acc[mf][nf][1] + b0;
                float y2 = acc[mf][nf][2] + b1, y3 = acc[mf][nf][3] + b1;
                mx0 = fmaxf(mx0, fmaxf(y0, y1)); mn0 = fminf(mn0, fminf(y0, y1));
                mx1 = fmaxf(mx1, fmaxf(y2, y3)); mn1 = fminf(mn1, fminf(y2, y3));
                s10 += y0 + y1; s20 += y0*y0 + y1*y1;
                s11 += y2 + y3; s21 += y2*y2 + y3*y3;
            }
            #pragma unroll
            for (int off = 1; off <= 2; off <<= 1) {
                mx0 = fmaxf(mx0, __shfl_xor_sync(0xffffffffu, mx0, off));
                mn0 = fminf(mn0, __shfl_xor_sync(0xffffffffu, mn0, off));
                mx1 = fmaxf(mx1, __shfl_xor_sync(0xffffffffu, mx1, off));
                mn1 = fminf(mn1, __shfl_xor_sync(0xffffffffu, mn1, off));
                s10 += __shfl_xor_sync(0xffffffffu, s10, off);
                s20 += __shfl_xor_sync(0xffffffffu, s20, off);
                s11 += __shfl_xor_sync(0xffffffffu, s11, off);
                s21 += __shfl_xor_sync(0xffffffffu, s21, off);
            }
            if ((lane & 3) == 0) {
                g_mx[(size_t)r*NG + grp]       = mx0;
                g_mn[(size_t)r*NG + grp]       = mn0;
                g_mx[(size_t)(r + 8)*NG + grp] = mx1;
                g_mn[(size_t)(r + 8)*NG + grp] = mn1;
                d1a[mf*2]   += (double)s10; d2a[mf*2]   += (double)s20;
                d1a[mf*2+1] += (double)s11; d2a[mf*2+1] += (double)s21;
            }
        }
    }

    if ((lane & 3) == 0) {
        #pragma unroll
        for (int q = 0; q < 4; ++q) {
            int r = wm*32 + (q >> 1)*16 + (q & 1)*8 + (lane >> 2);
            atomicAdd(&g_sum[3][r], d1a[q]);
            atomicAdd(&g_sq [3][r], d2a[q]);
        }
    }
}

// ---------------------------------------------------------------------------
__global__ void k_finalize(int layer, const float* __restrict__ gamma,
                           const float* __restrict__ beta, int cout)
{
    int c = threadIdx.x;
    if (c < cout) {
        double mean = g_sum[layer][c] / (double)PP;
        double var  = g_sq [layer][c] / (double)PP - mean*mean;
        double invs = rsqrt(var + 1e-5);
        double sc   = (double)gamma[c] * invs;
        g_scale[layer][c] = (float)sc;
        g_shift[layer][c] = (float)((double)beta[c] - mean * sc);
    }
}

// ---------------------------------------------------------------------------
__global__ void __launch_bounds__(256) k_out(float* __restrict__ out)
{
    int t = blockIdx.x * blockDim.x + threadIdx.x;
    if (t >= Bc*256*Sc) return;
    int s = t & (Sc - 1);
    int o = (t >> 11) & 255;
    int b = t >> 19;
    float sc = g_scale[3][o], sh = g_shift[3][o];
    int grp = b*Sc + s;
    float v = (sc > 0.f) ? g_mx[(size_t)o*NG + grp] : g_mn[(size_t)o*NG + grp];
    out[2*Bc*Sc*3 + t] = fmaxf(fmaf(v, sc, sh), 0.f);
}

// ---------------------------------------------------------------------------
extern "C" void kernel_launch(void* const* d_in, const int* in_sizes, int n_in,
                              void* d_out, int out_size)
{
    const float* contour = (const float*)d_in[0];
    const float* loa     = (const float*)d_in[1];
    const float* fmaps   = (const float*)d_in[2];
    const float* fe_w1   = (const float*)d_in[3];
    const float* fe_b1   = (const float*)d_in[4];
    const float* fe_g1   = (const float*)d_in[5];
    const float* fe_be1  = (const float*)d_in[6];
    const float* fe_w2   = (const float*)d_in[7];
    const float* fe_b2   = (const float*)d_in[8];
    const float* fe_g2   = (const float*)d_in[9];
    const float* fe_be2  = (const float*)d_in[10];
    const float* fl_w1   = (const float*)d_in[11];
    const float* fl_b1   = (const float*)d_in[12];
    const float* fl_g1   = (const float*)d_in[13];
    const float* fl_be1  = (const float*)d_in[14];
    const float* fl_w2   = (const float*)d_in[15];
    const float* fl_b2   = (const float*)d_in[16];
    const float* fl_g2   = (const float*)d_in[17];
    const float* fl_be2  = (const float*)d_in[18];
    float* out = (float*)d_out;

    cudaFuncSetAttribute(h_fl1, cudaFuncAttributeMaxDynamicSharedMemorySize, FL1_SMEM);
    cudaFuncSetAttribute(h_fl2, cudaFuncAttributeMaxDynamicSharedMemorySize, FL2_SMEM);

    const int PBLK = PP / 128;   // 4096

    k_rif<<<Bc*Sc/8, 256>>>(contour, loa, out);

    k_conv<8,   32,  32, 0, 0><<<dim3(PBLK, 1), 256>>>(fe_w1, fe_b1);
    k_finalize<<<1, 256>>>(0, fe_g1, fe_be1, 32);

    k_conv<32,  64,  64, 1, 1><<<dim3(PBLK, 1), 256>>>(fe_w2, fe_b2);
    k_finalize<<<1, 256>>>(1, fe_g2, fe_be2, 64);

    h_fl1<<<148, 512, FL1_SMEM>>>(fl_w1, fl_b1, fmaps);
    k_finalize<<<1, 256>>>(2, fl_g1, fl_be1, 128);

    h_fl2<<<148, 512, FL2_SMEM>>>(fl_w2, fl_b2);
    k_finalize<<<1, 256>>>(3, fl_g2, fl_be2, 256);

    k_out<<<(Bc*256*Sc + 255)/256, 256>>>(out);
}